// round 2
// baseline (speedup 1.0000x reference)
#include <cuda_runtime.h>
#include <cuda_fp16.h>
#include <math.h>

#define BATCH 256
#define NI    1152
#define NO    10
#define DOUT  16
#define DIN   8
#define OD    160          // NO * DOUT
#define CH    6            // routing i-chunks (192 i each)

// ---------------- scratch (device globals; no allocation) ----------------
__device__ __half g_xhat[(size_t)BATCH * NI * OD];   // [b][i][od] fp16, 94.5MB (L2-resident)
__device__ float  g_spart[72 * BATCH * OD];          // per-i-tile partial sums (fp32)
__device__ float  g_out0[BATCH * OD];                // squash(0.1 * sum_i xhat) == t for pass A
__device__ float  g_t1[BATCH * OD];                  // out0 + out1 == t for pass B
__device__ float  g_pacc[(size_t)BATCH * CH * OD];   // routing partial sums

// ---------------- packed fp32x2 helpers (sm_103a) ----------------
typedef unsigned long long ull;
__device__ __forceinline__ ull pack2(float x, float y) {
    ull r; asm("mov.b64 %0, {%1, %2};" : "=l"(r) : "f"(x), "f"(y)); return r;
}
__device__ __forceinline__ float2 unpk2(ull v) {
    float2 r; asm("mov.b64 {%0, %1}, %2;" : "=f"(r.x), "=f"(r.y) : "l"(v)); return r;
}
__device__ __forceinline__ ull ffma2(ull a, ull b, ull c) {
    ull d; asm("fma.rn.f32x2 %0, %1, %2, %3;" : "=l"(d) : "l"(a), "l"(b), "l"(c)); return d;
}
__device__ __forceinline__ ull fadd2(ull a, ull b) {
    ull d; asm("add.rn.f32x2 %0, %1, %2;" : "=l"(d) : "l"(a), "l"(b)); return d;
}

// =====================================================================
// Kernel 1: x_hat[b,i,od] = sum_c W[o,i,d,c] * x[b,i,c]   (fp16 out)
// CTA = 256 thr (8 warps), tile = 16 i's x 64 batches. Warp owns 8 batches,
// loops i: weights (40 floats) register-resident across the 8 batches,
// x read as smem broadcasts. Packed f32x2 FMAs. Also accumulates the
// per-i-tile partial sum (fp32) for s0.
// Lane l owns od in {4l..4l+3} (part1) and {128+l} (part2).
// =====================================================================
__global__ __launch_bounds__(256) void k1_xhat(const float* __restrict__ x,
                                               const float* __restrict__ w)
{
    __shared__ __align__(16) float xs[64 * 128];   // [bl][i*8+c], 32KB

    const int i0 = blockIdx.x * 16;
    const int b0 = blockIdx.y * 64;
    const int tid = threadIdx.x;

    // stage x tile: 64 b x 128 floats, coalesced float4
    for (int idx = tid; idx < 64 * 32; idx += 256) {
        int bl = idx >> 5, r4 = idx & 31;
        ((float4*)xs)[idx] =
            *(const float4*)&x[(size_t)(b0 + bl) * (NI * DIN) + (size_t)i0 * DIN + r4 * 4];
    }
    __syncthreads();

    const int warp = tid >> 5;
    const int lane = tid & 31;
    const int o1 = lane >> 2, d1 = (lane & 3) * 4;   // part1: od = 4*lane + dd
    const int o2 = 8 + (lane >> 4), d2 = lane & 15;  // part2: od = 128 + lane

    ull   sa01[8], sa23[8];
    float sa4[8];
    #pragma unroll
    for (int k = 0; k < 8; k++) { sa01[k] = 0ull; sa23[k] = 0ull; sa4[k] = 0.f; }

    for (int ii = 0; ii < 16; ii++) {
        const int i = i0 + ii;

        // weights -> registers (L1/L2-cached global reads)
        float wf1[32], wf2[8];
        const float4* wp1 = (const float4*)(w + ((size_t)(o1 * NI + i) * 16 + d1) * 8);
        const float4* wp2 = (const float4*)(w + ((size_t)(o2 * NI + i) * 16 + d2) * 8);
        #pragma unroll
        for (int k = 0; k < 8; k++) ((float4*)wf1)[k] = wp1[k];
        ((float4*)wf2)[0] = wp2[0];
        ((float4*)wf2)[1] = wp2[1];

        ull pw01[8], pw23[8];
        #pragma unroll
        for (int c = 0; c < 8; c++) {
            pw01[c] = pack2(wf1[c], wf1[8 + c]);
            pw23[c] = pack2(wf1[16 + c], wf1[24 + c]);
        }

        #pragma unroll 2
        for (int b8 = 0; b8 < 8; b8++) {
            const int bl = warp * 8 + b8;
            const float* xr = &xs[bl * 128 + ii * 8];
            ull a01 = 0ull, a23 = 0ull;
            float a4 = 0.f;
            #pragma unroll
            for (int c = 0; c < 8; c++) {
                float xc = xr[c];                 // smem broadcast
                ull xx = pack2(xc, xc);
                a01 = ffma2(pw01[c], xx, a01);
                a23 = ffma2(pw23[c], xx, a23);
                a4  = fmaf(wf2[c], xc, a4);
            }
            // store fp16
            size_t base = ((size_t)(b0 + bl) * NI + i) * OD;
            float2 f01 = unpk2(a01), f23 = unpk2(a23);
            __half2 h01 = __float22half2_rn(f01);
            __half2 h23 = __float22half2_rn(f23);
            union { __half2 h; unsigned int u; } ca, cb;
            ca.h = h01; cb.h = h23;
            *(uint2*)(g_xhat + base + 4 * lane) = make_uint2(ca.u, cb.u);
            g_xhat[base + 128 + lane] = __float2half_rn(a4);
            // accumulate fp32 partial
            sa01[b8] = fadd2(sa01[b8], a01);
            sa23[b8] = fadd2(sa23[b8], a23);
            sa4[b8] += a4;
        }
    }

    #pragma unroll
    for (int b8 = 0; b8 < 8; b8++) {
        const int b = b0 + warp * 8 + b8;
        size_t sb = ((size_t)blockIdx.x * BATCH + b) * OD;
        float2 s01 = unpk2(sa01[b8]), s23 = unpk2(sa23[b8]);
        *(float4*)&g_spart[sb + 4 * lane] = make_float4(s01.x, s01.y, s23.x, s23.y);
        g_spart[sb + 128 + lane] = sa4[b8];
    }
}

// =====================================================================
// Kernel 2: s0 = 0.1 * sum_i x_hat (reduce 72 partials); out0 = squash(s0)
// =====================================================================
__global__ void k2_out0()
{
    const int b  = blockIdx.x;
    const int od = threadIdx.x;     // 0..159
    float s = 0.f;
    #pragma unroll 8
    for (int k = 0; k < 72; k++)
        s += g_spart[((size_t)k * BATCH + b) * OD + od];
    s *= 0.1f;
    float v = s * s;
    v += __shfl_xor_sync(0xffffffffu, v, 8);
    v += __shfl_xor_sync(0xffffffffu, v, 4);
    v += __shfl_xor_sync(0xffffffffu, v, 2);
    v += __shfl_xor_sync(0xffffffffu, v, 1);
    float out = s * (v / (1.0f + v)) / (sqrtf(v) + 1e-8f);
    g_out0[b * OD + od] = out;
}

// =====================================================================
// Routing partial pass: for each i in the chunk:
//   logits e_o = <t_b, xh_{b,i,o,:}>, c = softmax_o(e), acc_o += c * xh
// grid (B, CH), block 256 = 64 groups of 4 lanes (lane j owns d-quarter).
// Writes g_pacc[b][ch][od] (fp32).
// =====================================================================
__global__ __launch_bounds__(256) void kp_pass(int useT1)
{
    __shared__ __align__(16) float t_s[OD];
    __shared__ float4 red[8][4][NO];

    const int b   = blockIdx.x;
    const int ch  = blockIdx.y;
    const int tid = threadIdx.x;
    const int lane = tid & 31;
    const int warp = tid >> 5;
    const int g = tid >> 2;
    const int j = tid & 3;

    const float* tsrc = useT1 ? g_t1 : g_out0;
    if (tid < OD) t_s[tid] = tsrc[b * OD + tid];
    __syncthreads();

    float4 acc[NO];
    #pragma unroll
    for (int o = 0; o < NO; o++) acc[o] = make_float4(0.f, 0.f, 0.f, 0.f);

    #pragma unroll
    for (int kk = 0; kk < 3; kk++) {
        const int i = ch * 192 + kk * 64 + g;
        const size_t base = ((size_t)b * NI + i) * OD + 4 * j;

        float4 xh[NO];
        #pragma unroll
        for (int o = 0; o < NO; o++) {
            uint2 v = *(const uint2*)(g_xhat + base + o * 16);
            union { unsigned int u; __half2 h; } ua, ub;
            ua.u = v.x; ub.u = v.y;
            float2 lo = __half22float2(ua.h);
            float2 hi = __half22float2(ub.h);
            xh[o] = make_float4(lo.x, lo.y, hi.x, hi.y);
        }

        float e[NO];
        #pragma unroll
        for (int o = 0; o < NO; o++) {
            float4 tv = *(const float4*)&t_s[o * 16 + 4 * j];
            float p = xh[o].x * tv.x;
            p = fmaf(xh[o].y, tv.y, p);
            p = fmaf(xh[o].z, tv.z, p);
            p = fmaf(xh[o].w, tv.w, p);
            p += __shfl_xor_sync(0xffffffffu, p, 1);
            p += __shfl_xor_sync(0xffffffffu, p, 2);
            e[o] = p;
        }
        float m = e[0];
        #pragma unroll
        for (int o = 1; o < NO; o++) m = fmaxf(m, e[o]);
        float sum = 0.f;
        #pragma unroll
        for (int o = 0; o < NO; o++) { e[o] = __expf(e[o] - m); sum += e[o]; }
        const float inv = 1.0f / sum;
        #pragma unroll
        for (int o = 0; o < NO; o++) {
            float c = e[o] * inv;
            acc[o].x = fmaf(c, xh[o].x, acc[o].x);
            acc[o].y = fmaf(c, xh[o].y, acc[o].y);
            acc[o].z = fmaf(c, xh[o].z, acc[o].z);
            acc[o].w = fmaf(c, xh[o].w, acc[o].w);
        }
    }

    // reduce across the 8 groups within each warp
    #pragma unroll
    for (int o = 0; o < NO; o++) {
        #pragma unroll
        for (int msk = 4; msk <= 16; msk <<= 1) {
            acc[o].x += __shfl_xor_sync(0xffffffffu, acc[o].x, msk);
            acc[o].y += __shfl_xor_sync(0xffffffffu, acc[o].y, msk);
            acc[o].z += __shfl_xor_sync(0xffffffffu, acc[o].z, msk);
            acc[o].w += __shfl_xor_sync(0xffffffffu, acc[o].w, msk);
        }
    }
    if (lane < 4) {
        #pragma unroll
        for (int o = 0; o < NO; o++) red[warp][lane][o] = acc[o];
    }
    __syncthreads();

    if (tid < OD) {
        const int od = tid;
        const int o  = od >> 4;
        const int dl = od & 15;
        const int jj = dl >> 2;
        const int dd = dl & 3;
        float s = 0.f;
        #pragma unroll
        for (int w8 = 0; w8 < 8; w8++)
            s += ((const float*)&red[w8][jj][o])[dd];
        g_pacc[((size_t)b * CH + ch) * OD + od] = s;
    }
}

// =====================================================================
// Routing reduce: sum CH partials -> s; out = squash(s).
// finalPass==0: g_t1 = g_out0 + out.   finalPass==1: dout = out.
// =====================================================================
__global__ void kr_reduce(float* __restrict__ dout, int finalPass)
{
    const int b  = blockIdx.x;
    const int od = threadIdx.x;     // 0..159
    float s = 0.f;
    #pragma unroll
    for (int ch = 0; ch < CH; ch++)
        s += g_pacc[((size_t)b * CH + ch) * OD + od];
    float v = s * s;
    v += __shfl_xor_sync(0xffffffffu, v, 8);
    v += __shfl_xor_sync(0xffffffffu, v, 4);
    v += __shfl_xor_sync(0xffffffffu, v, 2);
    v += __shfl_xor_sync(0xffffffffu, v, 1);
    float out = s * (v / (1.0f + v)) / (sqrtf(v) + 1e-8f);
    if (finalPass) dout[b * OD + od] = out;
    else           g_t1[b * OD + od] = g_out0[b * OD + od] + out;
}

// =====================================================================
extern "C" void kernel_launch(void* const* d_in, const int* in_sizes, int n_in,
                              void* d_out, int out_size)
{
    const float* x = (const float*)d_in[0];   // [256,1152,8]
    const float* w = (const float*)d_in[1];   // [10,1152,16,8]
    float* out = (float*)d_out;               // [256,10,16]

    k1_xhat<<<dim3(72, 4), 256>>>(x, w);
    k2_out0<<<BATCH, OD>>>();
    kp_pass<<<dim3(BATCH, CH), 256>>>(0);
    kr_reduce<<<BATCH, OD>>>(nullptr, 0);
    kp_pass<<<dim3(BATCH, CH), 256>>>(1);
    kr_reduce<<<BATCH, OD>>>(out, 1);
}

// round 3
// speedup vs baseline: 1.1615x; 1.1615x over previous
#include <cuda_runtime.h>
#include <cuda_fp16.h>
#include <math.h>

#define BATCH 256
#define NI    1152
#define NO    10
#define DOUT  16
#define DIN   8
#define OD    160          // NO * DOUT
#define CH    6            // routing i-chunks (192 i each)

// ---------------- scratch (device globals; no allocation) ----------------
__device__ __half g_xhat[(size_t)BATCH * NI * OD];   // [b][i][od] fp16, 94.5MB
__device__ float  g_out0[BATCH * OD];                // squash(0.1 * sum_i xhat) == t for pass A
__device__ float  g_t1[BATCH * OD];                  // out0 + out1 == t for pass B
__device__ float  g_pacc[(size_t)BATCH * CH * OD];   // routing partial sums

// ---------------- packed fp32x2 helpers (sm_103a) ----------------
typedef unsigned long long ull;
__device__ __forceinline__ ull pack2(float x, float y) {
    ull r; asm("mov.b64 %0, {%1, %2};" : "=l"(r) : "f"(x), "f"(y)); return r;
}
__device__ __forceinline__ float2 unpk2(ull v) {
    float2 r; asm("mov.b64 {%0, %1}, %2;" : "=f"(r.x), "=f"(r.y) : "l"(v)); return r;
}
__device__ __forceinline__ ull ffma2(ull a, ull b, ull c) {
    ull d; asm("fma.rn.f32x2 %0, %1, %2, %3;" : "=l"(d) : "l"(a), "l"(b), "l"(c)); return d;
}

// =====================================================================
// Kernel 1: x_hat[b,i,od] = sum_c W[o,i,d,c] * x[b,i,c]   (fp16 out)
// CTA = 320 threads, tile = 8 i x 64 b. Thread owns one (i, od-quad):
// its 32 weight floats live in 16 packed f32x2 registers for the whole
// 64-batch loop; x comes from smem as pre-packed (x,x) broadcasts.
// Stores: 8B per thread, contiguous 256B per warp.
// =====================================================================
#define K1_IT 8
#define K1_BT 64

__global__ __launch_bounds__(320) void k1_xhat(const float* __restrict__ x,
                                               const float* __restrict__ w)
{
    __shared__ ull xs2[K1_BT][K1_IT * DIN];   // (x,x) packed, 32KB

    const int i0 = blockIdx.x * K1_IT;
    const int b0 = blockIdx.y * K1_BT;
    const int tid = threadIdx.x;

    // stage x tile, pre-packed for ffma2
    for (int u = tid; u < K1_BT * 64; u += 320) {
        int bl = u >> 6, c64 = u & 63;
        float v = x[(size_t)(b0 + bl) * (NI * DIN) + (size_t)i0 * DIN + c64];
        xs2[bl][c64] = pack2(v, v);
    }

    const int il = tid / 40;          // 0..7
    const int q  = tid % 40;          // od quad: od = 4q..4q+3
    const int i  = i0 + il;
    const int o  = q >> 2;
    const int d0 = (q & 3) * 4;

    // 32 contiguous weight floats for this quad -> 16 packed regs
    const float4* wp = (const float4*)&w[(((size_t)o * NI + i) * 16 + d0) * 8];
    float wf[32];
    #pragma unroll
    for (int k = 0; k < 8; k++) ((float4*)wf)[k] = wp[k];
    ull pw01[8], pw23[8];
    #pragma unroll
    for (int c = 0; c < 8; c++) {
        pw01[c] = pack2(wf[c],      wf[8 + c]);
        pw23[c] = pack2(wf[16 + c], wf[24 + c]);
    }
    __syncthreads();

    const ull* xrow0 = &xs2[0][il * 8];
    #pragma unroll 2
    for (int b = 0; b < K1_BT; b++) {
        const ull* xr = xrow0 + (size_t)b * (K1_IT * DIN);
        ull a01 = 0ull, a23 = 0ull;
        #pragma unroll
        for (int c = 0; c < 8; c++) {
            ull xx = xr[c];                    // smem broadcast (pre-packed)
            a01 = ffma2(pw01[c], xx, a01);
            a23 = ffma2(pw23[c], xx, a23);
        }
        float2 f01 = unpk2(a01), f23 = unpk2(a23);
        __half2 h0 = __float22half2_rn(f01);
        __half2 h1 = __float22half2_rn(f23);
        union { __half2 h; unsigned int u; } ca, cb;
        ca.h = h0; cb.h = h1;
        size_t base = ((size_t)(b0 + b) * NI + i) * OD + 4 * q;
        *(uint2*)(g_xhat + base) = make_uint2(ca.u, cb.u);
    }
}

// =====================================================================
// Kernel s0: out0 = squash(0.1 * sum_i x_hat[b,i,:])  (reads fp16 xhat)
// CTA per b, 160 threads: thread owns (od-octet q8, i-residue ir),
// streams 144 rows with uint4 loads; smem reduce over the 8 residues.
// =====================================================================
__global__ __launch_bounds__(160) void k_s0()
{
    __shared__ float red[8][OD];
    const int b = blockIdx.x;
    const int t = threadIdx.x;
    const int q8 = t % 20;            // octet: od = q8*8 .. q8*8+7
    const int ir = t / 20;            // 0..7

    float acc[8];
    #pragma unroll
    for (int e = 0; e < 8; e++) acc[e] = 0.f;

    const size_t rowbase = (size_t)b * NI * OD + q8 * 8;
    #pragma unroll 4
    for (int k = 0; k < 144; k++) {
        const int i = ir + 8 * k;
        uint4 v = *(const uint4*)(g_xhat + rowbase + (size_t)i * OD);
        float2 p0 = __half22float2(*(__half2*)&v.x);
        float2 p1 = __half22float2(*(__half2*)&v.y);
        float2 p2 = __half22float2(*(__half2*)&v.z);
        float2 p3 = __half22float2(*(__half2*)&v.w);
        acc[0] += p0.x; acc[1] += p0.y; acc[2] += p1.x; acc[3] += p1.y;
        acc[4] += p2.x; acc[5] += p2.y; acc[6] += p3.x; acc[7] += p3.y;
    }
    #pragma unroll
    for (int e = 0; e < 8; e++) red[ir][q8 * 8 + e] = acc[e];
    __syncthreads();

    // t = od
    float s = 0.f;
    #pragma unroll
    for (int r = 0; r < 8; r++) s += red[r][t];
    s *= 0.1f;
    float v = s * s;
    v += __shfl_xor_sync(0xffffffffu, v, 8);
    v += __shfl_xor_sync(0xffffffffu, v, 4);
    v += __shfl_xor_sync(0xffffffffu, v, 2);
    v += __shfl_xor_sync(0xffffffffu, v, 1);
    g_out0[b * OD + t] = s * (v / (1.0f + v)) / (sqrtf(v) + 1e-8f);
}

// =====================================================================
// Routing partial pass. 64 groups of 4 lanes; lane j owns d-quarter.
// Phase 1 (logits): xh converted on the fly, t read from smem, xh NOT
// kept live. Phase 2 (accumulate): xh reloaded (L1 hit) after softmax.
// ~65 regs, no spills.
// =====================================================================
__global__ __launch_bounds__(256) void kp_pass(int useT1)
{
    __shared__ __align__(16) float t_s[OD];
    __shared__ float4 red[8][4][NO];

    const int b   = blockIdx.x;
    const int ch  = blockIdx.y;
    const int tid = threadIdx.x;
    const int lane = tid & 31;
    const int warp = tid >> 5;
    const int g = tid >> 2;
    const int j = tid & 3;

    const float* tsrc = useT1 ? g_t1 : g_out0;
    if (tid < OD) t_s[tid] = tsrc[b * OD + tid];
    __syncthreads();

    float4 acc[NO];
    #pragma unroll
    for (int o = 0; o < NO; o++) acc[o] = make_float4(0.f, 0.f, 0.f, 0.f);

    #pragma unroll
    for (int kk = 0; kk < 3; kk++) {
        const int i = ch * 192 + kk * 64 + g;
        const __half* p = g_xhat + ((size_t)b * NI + i) * OD + 4 * j;

        float e[NO];
        #pragma unroll
        for (int o = 0; o < NO; o++) {
            uint2 v = *(const uint2*)(p + o * 16);
            float2 lo = __half22float2(*(__half2*)&v.x);
            float2 hi = __half22float2(*(__half2*)&v.y);
            float4 tv = *(const float4*)&t_s[o * 16 + 4 * j];
            float pd = lo.x * tv.x;
            pd = fmaf(lo.y, tv.y, pd);
            pd = fmaf(hi.x, tv.z, pd);
            pd = fmaf(hi.y, tv.w, pd);
            pd += __shfl_xor_sync(0xffffffffu, pd, 1);
            pd += __shfl_xor_sync(0xffffffffu, pd, 2);
            e[o] = pd;
        }
        float m = e[0];
        #pragma unroll
        for (int o = 1; o < NO; o++) m = fmaxf(m, e[o]);
        float sum = 0.f;
        #pragma unroll
        for (int o = 0; o < NO; o++) { e[o] = __expf(e[o] - m); sum += e[o]; }
        const float inv = 1.0f / sum;
        #pragma unroll
        for (int o = 0; o < NO; o++) {
            uint2 v = *(const uint2*)(p + o * 16);   // L1 hit
            float2 lo = __half22float2(*(__half2*)&v.x);
            float2 hi = __half22float2(*(__half2*)&v.y);
            float c = e[o] * inv;
            acc[o].x = fmaf(c, lo.x, acc[o].x);
            acc[o].y = fmaf(c, lo.y, acc[o].y);
            acc[o].z = fmaf(c, hi.x, acc[o].z);
            acc[o].w = fmaf(c, hi.y, acc[o].w);
        }
    }

    // reduce across the 8 groups within each warp
    #pragma unroll
    for (int o = 0; o < NO; o++) {
        #pragma unroll
        for (int msk = 4; msk <= 16; msk <<= 1) {
            acc[o].x += __shfl_xor_sync(0xffffffffu, acc[o].x, msk);
            acc[o].y += __shfl_xor_sync(0xffffffffu, acc[o].y, msk);
            acc[o].z += __shfl_xor_sync(0xffffffffu, acc[o].z, msk);
            acc[o].w += __shfl_xor_sync(0xffffffffu, acc[o].w, msk);
        }
    }
    if (lane < 4) {
        #pragma unroll
        for (int o = 0; o < NO; o++) red[warp][lane][o] = acc[o];
    }
    __syncthreads();

    if (tid < OD) {
        const int od = tid;
        const int o  = od >> 4;
        const int dl = od & 15;
        const int jj = dl >> 2;
        const int dd = dl & 3;
        float s = 0.f;
        #pragma unroll
        for (int w8 = 0; w8 < 8; w8++)
            s += ((const float*)&red[w8][jj][o])[dd];
        g_pacc[((size_t)b * CH + ch) * OD + od] = s;
    }
}

// =====================================================================
// Routing reduce: sum CH partials -> squash. 4 batches per CTA.
// finalPass==0: g_t1 = g_out0 + out.   finalPass==1: dout = out.
// =====================================================================
__global__ __launch_bounds__(640) void kr_reduce(float* __restrict__ dout, int finalPass)
{
    const int tid = threadIdx.x;
    const int b  = blockIdx.x * 4 + tid / OD;
    const int od = tid % OD;
    float s = 0.f;
    #pragma unroll
    for (int ch = 0; ch < CH; ch++)
        s += g_pacc[((size_t)b * CH + ch) * OD + od];
    float v = s * s;
    v += __shfl_xor_sync(0xffffffffu, v, 8);
    v += __shfl_xor_sync(0xffffffffu, v, 4);
    v += __shfl_xor_sync(0xffffffffu, v, 2);
    v += __shfl_xor_sync(0xffffffffu, v, 1);
    float out = s * (v / (1.0f + v)) / (sqrtf(v) + 1e-8f);
    if (finalPass) dout[b * OD + od] = out;
    else           g_t1[b * OD + od] = g_out0[b * OD + od] + out;
}

// =====================================================================
extern "C" void kernel_launch(void* const* d_in, const int* in_sizes, int n_in,
                              void* d_out, int out_size)
{
    const float* x = (const float*)d_in[0];   // [256,1152,8]
    const float* w = (const float*)d_in[1];   // [10,1152,16,8]
    float* out = (float*)d_out;               // [256,10,16]

    k1_xhat<<<dim3(NI / K1_IT, BATCH / K1_BT), 320>>>(x, w);
    k_s0<<<BATCH, 160>>>();
    kp_pass<<<dim3(BATCH, CH), 256>>>(0);
    kr_reduce<<<BATCH / 4, 640>>>(nullptr, 0);
    kp_pass<<<dim3(BATCH, CH), 256>>>(1);
    kr_reduce<<<BATCH / 4, 640>>>(out, 1);
}

// round 5
// speedup vs baseline: 1.7361x; 1.4947x over previous
#include <cuda_runtime.h>
#include <cuda_fp16.h>
#include <cstdint>
#include <math.h>

#define BATCH 256
#define NI    1152
#define NO    10
#define DOUT  16
#define DIN   8
#define OD    160          // NO * DOUT

// ---------------- scratch ----------------
__device__ __half g_xhat[(size_t)BATCH * NI * OD];   // [b][i][od] fp16, 94.5MB

// ---------------- packed fp32x2 helpers (sm_103a) ----------------
typedef unsigned long long ull;
__device__ __forceinline__ ull pack2(float x, float y) {
    ull r; asm("mov.b64 %0, {%1, %2};" : "=l"(r) : "f"(x), "f"(y)); return r;
}
__device__ __forceinline__ float2 unpk2(ull v) {
    float2 r; asm("mov.b64 {%0, %1}, %2;" : "=f"(r.x), "=f"(r.y) : "l"(v)); return r;
}
__device__ __forceinline__ ull ffma2(ull a, ull b, ull c) {
    ull d; asm("fma.rn.f32x2 %0, %1, %2, %3;" : "=l"(d) : "l"(a), "l"(b), "l"(c)); return d;
}

// ---------------- cluster helpers ----------------
__device__ __forceinline__ void cluster_sync_() {
    asm volatile("barrier.cluster.arrive.aligned;" ::: "memory");
    asm volatile("barrier.cluster.wait.aligned;" ::: "memory");
}
__device__ __forceinline__ unsigned int smem_u32(const void* p) {
    unsigned int a;
    asm("{ .reg .u64 t; cvta.to.shared.u64 t, %1; cvt.u32.u64 %0, t; }" : "=r"(a) : "l"(p));
    return a;
}
__device__ __forceinline__ void st_remote_f32(unsigned int saddr, unsigned int peer, float v) {
    unsigned int ra;
    asm volatile("mapa.shared::cluster.u32 %0, %1, %2;" : "=r"(ra) : "r"(saddr), "r"(peer));
    asm volatile("st.shared::cluster.f32 [%0], %1;" :: "r"(ra), "f"(v) : "memory");
}

// =====================================================================
// Kernel 1: x_hat fp16, thread owns (i, od-quad),
// weights register-resident across 64 batches.
// =====================================================================
#define K1_IT 8
#define K1_BT 64

__global__ __launch_bounds__(320) void k1_xhat(const float* __restrict__ x,
                                               const float* __restrict__ w)
{
    __shared__ ull xs2[K1_BT][K1_IT * DIN];   // (x,x) packed, 32KB

    const int i0 = blockIdx.x * K1_IT;
    const int b0 = blockIdx.y * K1_BT;
    const int tid = threadIdx.x;

    for (int u = tid; u < K1_BT * 64; u += 320) {
        int bl = u >> 6, c64 = u & 63;
        float v = x[(size_t)(b0 + bl) * (NI * DIN) + (size_t)i0 * DIN + c64];
        xs2[bl][c64] = pack2(v, v);
    }

    const int il = tid / 40;
    const int q  = tid % 40;
    const int i  = i0 + il;
    const int o  = q >> 2;
    const int d0 = (q & 3) * 4;

    const float4* wp = (const float4*)&w[(((size_t)o * NI + i) * 16 + d0) * 8];
    float wf[32];
    #pragma unroll
    for (int k = 0; k < 8; k++) ((float4*)wf)[k] = wp[k];
    ull pw01[8], pw23[8];
    #pragma unroll
    for (int c = 0; c < 8; c++) {
        pw01[c] = pack2(wf[c],      wf[8 + c]);
        pw23[c] = pack2(wf[16 + c], wf[24 + c]);
    }
    __syncthreads();

    const ull* xrow0 = &xs2[0][il * 8];
    #pragma unroll 2
    for (int b = 0; b < K1_BT; b++) {
        const ull* xr = xrow0 + (size_t)b * (K1_IT * DIN);
        ull a01 = 0ull, a23 = 0ull;
        #pragma unroll
        for (int c = 0; c < 8; c++) {
            ull xx = xr[c];
            a01 = ffma2(pw01[c], xx, a01);
            a23 = ffma2(pw23[c], xx, a23);
        }
        float2 f01 = unpk2(a01), f23 = unpk2(a23);
        __half2 h0 = __float22half2_rn(f01);
        __half2 h1 = __float22half2_rn(f23);
        union { __half2 h; unsigned int u; } ca, cb;
        ca.h = h0; cb.h = h1;
        size_t base = ((size_t)(b0 + b) * NI + i) * OD + 4 * q;
        *(uint2*)(g_xhat + base) = make_uint2(ca.u, cb.u);
    }
}

// =====================================================================
// Kernel 2: fused routing. Cluster of 2 CTAs = one batch; each CTA holds
// 576 i-rows of x_hat in smem (336B padded rows) and does s0 + both
// routing passes from smem. 160-float partials exchanged via DSMEM.
// =====================================================================
#define K2_THREADS 384
#define NIH   576             // i-rows per CTA
#define ROWB  336             // padded row stride in bytes (160*2 -> 336)
#define NG    96              // 4-lane groups (384/4)
#define NW    12              // warps

// dynamic smem layout (bytes)
#define XH_OFF   0
#define XH_SZ    (NIH * ROWB)                  // 193,536
#define S0_OFF   (XH_OFF + XH_SZ)              // [16][160] f32
#define S0_SZ    (16 * OD * 4)                 // 10,240
#define RED_OFF  (S0_OFF + S0_SZ)              // [12][4][10] float4
#define RED_SZ   (NW * 4 * NO * 16)            // 7,680
#define SLOT_OFF (RED_OFF + RED_SZ)            // [6][160] f32
#define SLOT_SZ  (6 * OD * 4)                  // 3,840
#define TS_OFF   (SLOT_OFF + SLOT_SZ)          // [160] f32
#define TS_SZ    (OD * 4)
#define K2_SMEM  (TS_OFF + TS_SZ)              // 215,936 B

__device__ __forceinline__ float squash16(float s) {
    float v = s * s;
    v += __shfl_xor_sync(0xffffffffu, v, 8);
    v += __shfl_xor_sync(0xffffffffu, v, 4);
    v += __shfl_xor_sync(0xffffffffu, v, 2);
    v += __shfl_xor_sync(0xffffffffu, v, 1);
    return s * (v / (1.0f + v)) / (sqrtf(v) + 1e-8f);
}

__global__ __cluster_dims__(2, 1, 1) __launch_bounds__(K2_THREADS, 1)
void k2_route(float* __restrict__ dout)
{
    extern __shared__ __align__(16) char sm[];
    char*  xhb  = sm + XH_OFF;
    float* s0b  = (float*)(sm + S0_OFF);
    float* redf = (float*)(sm + RED_OFF);
    float* slot = (float*)(sm + SLOT_OFF);
    float* t_s  = (float*)(sm + TS_OFF);

    const int cta = blockIdx.x;
    const int b   = cta >> 1;
    const unsigned int rank = cta & 1;
    const unsigned int peer = rank ^ 1;
    const int tid  = threadIdx.x;
    const int lane = tid & 31;
    const int warp = tid >> 5;
    const int g = tid >> 2;
    const int j = tid & 3;

    // ---- copy my 576-row slice into smem (padded rows) ----
    const __half* src = g_xhat + ((size_t)b * NI + (size_t)rank * NIH) * OD;
    #pragma unroll 5
    for (int e = tid; e < NIH * 20; e += K2_THREADS) {
        int row = e / 20, u = e % 20;
        uint4 v = *(const uint4*)(src + (size_t)e * 8);
        *(uint4*)(xhb + row * ROWB + u * 16) = v;
    }
    __syncthreads();

    // ---- s0 partial: sum over my 576 i ----
    if (tid < 320) {
        const int q  = tid % 20;    // od octet
        const int ir = tid / 20;    // 0..15
        float a[8];
        #pragma unroll
        for (int e = 0; e < 8; e++) a[e] = 0.f;
        #pragma unroll 4
        for (int k = 0; k < NIH / 16; k++) {
            const int row = ir + 16 * k;
            uint4 v = *(const uint4*)(xhb + row * ROWB + q * 16);
            float2 p0 = __half22float2(*(__half2*)&v.x);
            float2 p1 = __half22float2(*(__half2*)&v.y);
            float2 p2 = __half22float2(*(__half2*)&v.z);
            float2 p3 = __half22float2(*(__half2*)&v.w);
            a[0] += p0.x; a[1] += p0.y; a[2] += p1.x; a[3] += p1.y;
            a[4] += p2.x; a[5] += p2.y; a[6] += p3.x; a[7] += p3.y;
        }
        #pragma unroll
        for (int e = 0; e < 8; e++) s0b[ir * OD + q * 8 + e] = a[e];
    }
    __syncthreads();

    float myval = 0.f;
    if (tid < OD) {
        #pragma unroll
        for (int r = 0; r < 16; r++) myval += s0b[r * OD + tid];
    }
    // ---- exchange 0 -> s0; out0 ----
    if (tid < OD) {
        slot[(0 * 2 + rank) * OD + tid] = myval;
        st_remote_f32(smem_u32(&slot[(0 * 2 + rank) * OD + tid]), peer, myval);
    }
    cluster_sync_();
    float out0 = 0.f;
    if (tid < OD) {
        float s = (slot[0 * OD + tid] + slot[1 * OD + tid]) * 0.1f;
        out0 = squash16(s);
        t_s[tid] = out0;
    }
    __syncthreads();

    // ---- two routing passes ----
    #pragma unroll 1
    for (int pass = 0; pass < 2; pass++) {
        float4 t4[NO];
        #pragma unroll
        for (int o = 0; o < NO; o++)
            t4[o] = *(const float4*)&t_s[o * 16 + 4 * j];

        float4 acc[NO];
        #pragma unroll
        for (int o = 0; o < NO; o++) acc[o] = make_float4(0.f, 0.f, 0.f, 0.f);

        #pragma unroll 1
        for (int k = 0; k < NIH / NG; k++) {
            const int row = g + NG * k;
            const char* p = xhb + row * ROWB + j * 8;

            float4 xh[NO];
            float e[NO];
            #pragma unroll
            for (int o = 0; o < NO; o++) {
                uint2 v = *(const uint2*)(p + o * 32);
                float2 lo = __half22float2(*(__half2*)&v.x);
                float2 hi = __half22float2(*(__half2*)&v.y);
                xh[o] = make_float4(lo.x, lo.y, hi.x, hi.y);
                float pd = xh[o].x * t4[o].x;
                pd = fmaf(xh[o].y, t4[o].y, pd);
                pd = fmaf(xh[o].z, t4[o].z, pd);
                pd = fmaf(xh[o].w, t4[o].w, pd);
                pd += __shfl_xor_sync(0xffffffffu, pd, 1);
                pd += __shfl_xor_sync(0xffffffffu, pd, 2);
                e[o] = pd;
            }
            float m = e[0];
            #pragma unroll
            for (int o = 1; o < NO; o++) m = fmaxf(m, e[o]);
            float sum = 0.f;
            #pragma unroll
            for (int o = 0; o < NO; o++) { e[o] = __expf(e[o] - m); sum += e[o]; }
            const float inv = 1.0f / sum;
            #pragma unroll
            for (int o = 0; o < NO; o++) {
                float c = e[o] * inv;
                acc[o].x = fmaf(c, xh[o].x, acc[o].x);
                acc[o].y = fmaf(c, xh[o].y, acc[o].y);
                acc[o].z = fmaf(c, xh[o].z, acc[o].z);
                acc[o].w = fmaf(c, xh[o].w, acc[o].w);
            }
        }

        // reduce acc over the 8 groups within each warp
        #pragma unroll
        for (int o = 0; o < NO; o++) {
            #pragma unroll
            for (int msk = 4; msk <= 16; msk <<= 1) {
                acc[o].x += __shfl_xor_sync(0xffffffffu, acc[o].x, msk);
                acc[o].y += __shfl_xor_sync(0xffffffffu, acc[o].y, msk);
                acc[o].z += __shfl_xor_sync(0xffffffffu, acc[o].z, msk);
                acc[o].w += __shfl_xor_sync(0xffffffffu, acc[o].w, msk);
            }
        }
        if (lane < 4) {
            float4* rw = (float4*)redf + (warp * 4 + lane) * NO;
            #pragma unroll
            for (int o = 0; o < NO; o++) rw[o] = acc[o];
        }
        __syncthreads();

        float pv = 0.f;
        if (tid < OD) {
            const int o  = tid >> 4;
            const int dl = tid & 15;
            const int jj = dl >> 2;
            const int dd = dl & 3;
            #pragma unroll
            for (int w8 = 0; w8 < NW; w8++)
                pv += redf[((w8 * 4 + jj) * NO + o) * 4 + dd];
        }
        const int ex = 1 + pass;
        if (tid < OD) {
            slot[(ex * 2 + rank) * OD + tid] = pv;
            st_remote_f32(smem_u32(&slot[(ex * 2 + rank) * OD + tid]), peer, pv);
        }
        cluster_sync_();
        if (tid < OD) {
            float s = slot[ex * 2 * OD + tid] + slot[(ex * 2 + 1) * OD + tid];
            float out = squash16(s);
            if (pass == 0) t_s[tid] = out0 + out;
            else if (rank == 0) dout[b * OD + tid] = out;
        }
        __syncthreads();
    }
}

// =====================================================================
extern "C" void kernel_launch(void* const* d_in, const int* in_sizes, int n_in,
                              void* d_out, int out_size)
{
    const float* x = (const float*)d_in[0];   // [256,1152,8]
    const float* w = (const float*)d_in[1];   // [10,1152,16,8]
    float* out = (float*)d_out;               // [256,10,16]

    cudaFuncSetAttribute(k2_route, cudaFuncAttributeMaxDynamicSharedMemorySize, K2_SMEM);

    k1_xhat<<<dim3(NI / K1_IT, BATCH / K1_BT), 320>>>(x, w);
    k2_route<<<2 * BATCH, K2_THREADS, K2_SMEM>>>(out);
}